// round 1
// baseline (speedup 1.0000x reference)
#include <cuda_runtime.h>
#include <math.h>

#define Bv   2
#define Tv   2048
#define Dv   768
#define Hv   12
#define HDv  64
#define Lv   4
#define DFv  3072
#define Vv   32000
#define Mv   (Bv*Tv)        /* 4096 rows */
#define QKVN (3*Hv*HDv)     /* 2304 */

// ---------------- scratch (static device globals; no allocs) ----------------
__device__ float g_x  [Mv*Dv];     // residual stream
__device__ float g_ln [Mv*Dv];     // layernorm output
__device__ float g_qkv[Mv*QKVN];   // qkv projection
__device__ float g_att[Mv*Dv];     // attention output
__device__ float g_ff [Mv*DFv];    // ffn hidden

// ---------------- embedding ----------------
__global__ void embed_k(const int* __restrict__ ids, const float* __restrict__ te,
                        const float* __restrict__ pe, float* __restrict__ x) {
    int i = blockIdx.x * blockDim.x + threadIdx.x;
    if (i >= Mv * Dv) return;
    int r = i / Dv, d = i - r * Dv;
    int t = r % Tv;
    x[i] = te[(size_t)ids[r] * Dv + d] + pe[(size_t)t * Dv + d];
}

// ---------------- layernorm: one block (256 thr) per row of 768 ----------------
__global__ void ln_k(const float* __restrict__ x, const float* __restrict__ s,
                     const float* __restrict__ bb, float* __restrict__ y) {
    int r = blockIdx.x;
    const float* xr = x + (size_t)r * Dv;
    float*       yr = y + (size_t)r * Dv;
    __shared__ float red[8];
    int tid = threadIdx.x; // 256
    float v0 = xr[tid], v1 = xr[tid + 256], v2 = xr[tid + 512];
    float sum = v0 + v1 + v2;
    #pragma unroll
    for (int o = 16; o; o >>= 1) sum += __shfl_xor_sync(0xffffffffu, sum, o);
    if ((tid & 31) == 0) red[tid >> 5] = sum;
    __syncthreads();
    float mu = (red[0]+red[1]+red[2]+red[3]+red[4]+red[5]+red[6]+red[7]) * (1.0f/Dv);
    float d0 = v0 - mu, d1 = v1 - mu, d2 = v2 - mu;
    float sq = d0*d0 + d1*d1 + d2*d2;
    __syncthreads();
    #pragma unroll
    for (int o = 16; o; o >>= 1) sq += __shfl_xor_sync(0xffffffffu, sq, o);
    if ((tid & 31) == 0) red[tid >> 5] = sq;
    __syncthreads();
    float var = (red[0]+red[1]+red[2]+red[3]+red[4]+red[5]+red[6]+red[7]) * (1.0f/Dv);
    float rstd = rsqrtf(var + 1e-5f);
    yr[tid      ] = d0 * rstd * s[tid      ] + bb[tid      ];
    yr[tid + 256] = d1 * rstd * s[tid + 256] + bb[tid + 256];
    yr[tid + 512] = d2 * rstd * s[tid + 512] + bb[tid + 512];
}

// ---------------- GEMM: C[M,N] = A[M,K] @ B (+bias)(+silu)(+res) ----------------
// TRANSB=false: B is [K,N] row-major.  TRANSB=true: B is [N,K] row-major (C = A·B^T).
// 128x128 tile, BK=8, 256 threads, 8x8 per thread. Requires M%128==N%128==K%8==0.
template <bool TRANSB, int ACT, bool RES>
__global__ __launch_bounds__(256) void gemm_k(
    const float* __restrict__ A, const float* __restrict__ B,
    const float* __restrict__ bias, const float* __restrict__ res,
    float* __restrict__ C, int M, int N, int K) {
    __shared__ float As[8][128];
    __shared__ float Bs[8][128];
    int n0 = blockIdx.x * 128, m0 = blockIdx.y * 128;
    int tid = threadIdx.x;
    int tx = tid & 15, ty = tid >> 4;
    float acc[8][8] = {};
    for (int k0 = 0; k0 < K; k0 += 8) {
        // A tile: thread -> (row = tid/2, 4 ks)
        {
            int am = tid >> 1, ak = (tid & 1) * 4;
            float4 a4 = *(const float4*)(A + (size_t)(m0 + am) * K + k0 + ak);
            As[ak + 0][am] = a4.x; As[ak + 1][am] = a4.y;
            As[ak + 2][am] = a4.z; As[ak + 3][am] = a4.w;
        }
        if (!TRANSB) {
            int bk = tid >> 5, bn = (tid & 31) * 4;
            float4 b4 = *(const float4*)(B + (size_t)(k0 + bk) * N + n0 + bn);
            *(float4*)&Bs[bk][bn] = b4;
        } else {
            int bn = tid >> 1, bk = (tid & 1) * 4;
            float4 b4 = *(const float4*)(B + (size_t)(n0 + bn) * K + k0 + bk);
            Bs[bk + 0][bn] = b4.x; Bs[bk + 1][bn] = b4.y;
            Bs[bk + 2][bn] = b4.z; Bs[bk + 3][bn] = b4.w;
        }
        __syncthreads();
        #pragma unroll
        for (int kk = 0; kk < 8; kk++) {
            float a[8], b[8];
            #pragma unroll
            for (int i = 0; i < 8; i++) a[i] = As[kk][ty * 8 + i];
            #pragma unroll
            for (int j = 0; j < 8; j++) b[j] = Bs[kk][tx * 8 + j];
            #pragma unroll
            for (int i = 0; i < 8; i++)
                #pragma unroll
                for (int j = 0; j < 8; j++)
                    acc[i][j] = fmaf(a[i], b[j], acc[i][j]);
        }
        __syncthreads();
    }
    #pragma unroll
    for (int i = 0; i < 8; i++) {
        int m = m0 + ty * 8 + i;
        #pragma unroll
        for (int j = 0; j < 8; j++) {
            int n = n0 + tx * 8 + j;
            float v = acc[i][j];
            if (bias) v += bias[n];
            if (ACT == 1) v = v * (1.0f / (1.0f + __expf(-v)));   // silu
            if (RES) v += res[(size_t)m * N + n];
            C[(size_t)m * N + n] = v;
        }
    }
}

// ---------------- attention: one block (128 thr) per (b, h, query) ----------------
__global__ void attn_k(const float* __restrict__ qkv, float* __restrict__ out) {
    int t = blockIdx.x, h = blockIdx.y, b = blockIdx.z;
    int row = b * Tv + t;
    __shared__ float qs[64];
    __shared__ float sc[128];
    __shared__ float red[4];
    int tid = threadIdx.x; // 128
    if (tid < 64) qs[tid] = qkv[(size_t)row * QKVN + h * HDv + tid] * 0.125f; // 1/sqrt(64)
    __syncthreads();
    float m = -1e30f, l = 0.0f, acc = 0.0f;
    const float* kbase = qkv + (size_t)(b * Tv) * QKVN + Hv * HDv     + h * HDv;
    const float* vbase = qkv + (size_t)(b * Tv) * QKVN + 2 * Hv * HDv + h * HDv;
    for (int c0 = 0; c0 <= t; c0 += 128) {
        int Lc = min(128, t + 1 - c0);
        float s = -1e30f;
        if (tid < Lc) {
            const float* kp = kbase + (size_t)(c0 + tid) * QKVN;
            float a0 = 0, a1 = 0, a2 = 0, a3 = 0;
            #pragma unroll
            for (int d = 0; d < 64; d += 4) {
                float4 k4 = *(const float4*)(kp + d);
                a0 = fmaf(qs[d    ], k4.x, a0);
                a1 = fmaf(qs[d + 1], k4.y, a1);
                a2 = fmaf(qs[d + 2], k4.z, a2);
                a3 = fmaf(qs[d + 3], k4.w, a3);
            }
            s = a0 + a1 + a2 + a3;
        }
        // block max
        float wmax = s;
        #pragma unroll
        for (int o = 16; o; o >>= 1) wmax = fmaxf(wmax, __shfl_xor_sync(0xffffffffu, wmax, o));
        if ((tid & 31) == 0) red[tid >> 5] = wmax;
        __syncthreads();
        float m_new = fmaxf(fmaxf(red[0], red[1]), fmaxf(red[2], red[3]));
        m_new = fmaxf(m, m_new);
        float p = (tid < Lc) ? __expf(s - m_new) : 0.0f;
        sc[tid] = p;
        float ws = p;
        #pragma unroll
        for (int o = 16; o; o >>= 1) ws += __shfl_xor_sync(0xffffffffu, ws, o);
        __syncthreads();           // WAR on red; also publishes sc[]
        if ((tid & 31) == 0) red[tid >> 5] = ws;
        __syncthreads();
        float csum = red[0] + red[1] + red[2] + red[3];
        float scale = __expf(m - m_new);
        l = l * scale + csum;
        m = m_new;
        if (tid < 64) {
            const float* vp = vbase + (size_t)c0 * QKVN + tid;
            float a2 = acc * scale;
            #pragma unroll 4
            for (int j = 0; j < Lc; j++) a2 = fmaf(sc[j], vp[(size_t)j * QKVN], a2);
            acc = a2;
        }
        __syncthreads();           // WAR on sc before next chunk
    }
    if (tid < 64) out[(size_t)row * Dv + h * HDv + tid] = acc / l;
}

// ---------------- driver ----------------
extern "C" void kernel_launch(void* const* d_in, const int* in_sizes, int n_in,
                              void* d_out, int out_size) {
    const int*   ids   = (const int*)  d_in[0];
    const float* te    = (const float*)d_in[1];
    const float* pe    = (const float*)d_in[2];
    const float* ln1_s = (const float*)d_in[3];
    const float* ln1_b = (const float*)d_in[4];
    const float* qkv_w = (const float*)d_in[5];
    const float* qkv_b = (const float*)d_in[6];
    const float* out_w = (const float*)d_in[7];
    const float* out_b = (const float*)d_in[8];
    const float* ln2_s = (const float*)d_in[9];
    const float* ln2_b = (const float*)d_in[10];
    const float* up_w  = (const float*)d_in[11];
    const float* up_b  = (const float*)d_in[12];
    const float* dn_w  = (const float*)d_in[13];
    const float* dn_b  = (const float*)d_in[14];
    const float* lnf_s = (const float*)d_in[15];
    const float* lnf_b = (const float*)d_in[16];
    float* logits = (float*)d_out;

    float *x, *lnb, *qkv, *att, *ff;
    cudaGetSymbolAddress((void**)&x,   g_x);
    cudaGetSymbolAddress((void**)&lnb, g_ln);
    cudaGetSymbolAddress((void**)&qkv, g_qkv);
    cudaGetSymbolAddress((void**)&att, g_att);
    cudaGetSymbolAddress((void**)&ff,  g_ff);

    embed_k<<<(Mv * Dv + 255) / 256, 256>>>(ids, te, pe, x);

    for (int i = 0; i < Lv; i++) {
        ln_k<<<Mv, 256>>>(x, ln1_s + (size_t)i * Dv, ln1_b + (size_t)i * Dv, lnb);
        gemm_k<false, 0, false><<<dim3(QKVN / 128, Mv / 128), 256>>>(
            lnb, qkv_w + (size_t)i * Dv * QKVN, qkv_b + (size_t)i * QKVN,
            nullptr, qkv, Mv, QKVN, Dv);
        attn_k<<<dim3(Tv, Hv, Bv), 128>>>(qkv, att);
        gemm_k<false, 0, true><<<dim3(Dv / 128, Mv / 128), 256>>>(
            att, out_w + (size_t)i * Dv * Dv, out_b + (size_t)i * Dv,
            x, x, Mv, Dv, Dv);
        ln_k<<<Mv, 256>>>(x, ln2_s + (size_t)i * Dv, ln2_b + (size_t)i * Dv, lnb);
        gemm_k<false, 1, false><<<dim3(DFv / 128, Mv / 128), 256>>>(
            lnb, up_w + (size_t)i * Dv * DFv, up_b + (size_t)i * DFv,
            nullptr, ff, Mv, DFv, Dv);
        gemm_k<false, 0, true><<<dim3(Dv / 128, Mv / 128), 256>>>(
            ff, dn_w + (size_t)i * DFv * Dv, dn_b + (size_t)i * Dv,
            x, x, Mv, Dv, DFv);
    }

    ln_k<<<Mv, 256>>>(x, lnf_s, lnf_b, lnb);
    // logits = lnf(x) @ te^T   (tied head, no bias)
    gemm_k<true, 0, false><<<dim3(Vv / 128, Mv / 128), 256>>>(
        lnb, te, nullptr, nullptr, logits, Mv, Vv, Dv);
}

// round 2
// speedup vs baseline: 1.3213x; 1.3213x over previous
#include <cuda_runtime.h>
#include <math.h>

#define Bv   2
#define Tv   2048
#define Dv   768
#define Hv   12
#define HDv  64
#define Lv   4
#define DFv  3072
#define Vv   32000
#define Mv   (Bv*Tv)        /* 4096 rows */
#define QKVN (3*Hv*HDv)     /* 2304 */

// ---------------- scratch (static device globals; no allocs) ----------------
__device__ float g_x  [Mv*Dv];     // residual stream
__device__ float g_ln [Mv*Dv];     // layernorm output
__device__ float g_qkv[Mv*QKVN];   // qkv projection
__device__ float g_att[Mv*Dv];     // attention output
__device__ float g_ff [Mv*DFv];    // ffn hidden

// ---------------- embedding ----------------
__global__ void embed_k(const int* __restrict__ ids, const float* __restrict__ te,
                        const float* __restrict__ pe, float* __restrict__ x) {
    int i = blockIdx.x * blockDim.x + threadIdx.x;
    if (i >= Mv * Dv) return;
    int r = i / Dv, d = i - r * Dv;
    int t = r % Tv;
    x[i] = te[(size_t)ids[r] * Dv + d] + pe[(size_t)t * Dv + d];
}

// ---------------- layernorm: one block (256 thr) per row of 768 ----------------
__global__ void ln_k(const float* __restrict__ x, const float* __restrict__ s,
                     const float* __restrict__ bb, float* __restrict__ y) {
    int r = blockIdx.x;
    const float* xr = x + (size_t)r * Dv;
    float*       yr = y + (size_t)r * Dv;
    __shared__ float red[8];
    int tid = threadIdx.x; // 256
    float v0 = xr[tid], v1 = xr[tid + 256], v2 = xr[tid + 512];
    float sum = v0 + v1 + v2;
    #pragma unroll
    for (int o = 16; o; o >>= 1) sum += __shfl_xor_sync(0xffffffffu, sum, o);
    if ((tid & 31) == 0) red[tid >> 5] = sum;
    __syncthreads();
    float mu = (red[0]+red[1]+red[2]+red[3]+red[4]+red[5]+red[6]+red[7]) * (1.0f/Dv);
    float d0 = v0 - mu, d1 = v1 - mu, d2 = v2 - mu;
    float sq = d0*d0 + d1*d1 + d2*d2;
    __syncthreads();
    #pragma unroll
    for (int o = 16; o; o >>= 1) sq += __shfl_xor_sync(0xffffffffu, sq, o);
    if ((tid & 31) == 0) red[tid >> 5] = sq;
    __syncthreads();
    float var = (red[0]+red[1]+red[2]+red[3]+red[4]+red[5]+red[6]+red[7]) * (1.0f/Dv);
    float rstd = rsqrtf(var + 1e-5f);
    yr[tid      ] = d0 * rstd * s[tid      ] + bb[tid      ];
    yr[tid + 256] = d1 * rstd * s[tid + 256] + bb[tid + 256];
    yr[tid + 512] = d2 * rstd * s[tid + 512] + bb[tid + 512];
}

// ---------------- TF32 helpers ----------------
__device__ __forceinline__ unsigned f2t(float f) {
    unsigned u; asm("cvt.rna.tf32.f32 %0, %1;" : "=r"(u) : "f"(f)); return u;
}
__device__ __forceinline__ void mma_tf32(float* c, const unsigned* a, const unsigned* b) {
    asm volatile(
        "mma.sync.aligned.m16n8k8.row.col.f32.tf32.tf32.f32 "
        "{%0,%1,%2,%3}, {%4,%5,%6,%7}, {%8,%9}, {%0,%1,%2,%3};\n"
        : "+f"(c[0]), "+f"(c[1]), "+f"(c[2]), "+f"(c[3])
        : "r"(a[0]), "r"(a[1]), "r"(a[2]), "r"(a[3]), "r"(b[0]), "r"(b[1]));
}

// ---------------- Tensor-core GEMM: C[M,N] = A[M,K] @ B (+bias)(+silu)(+res) ----
// TRANSB=false: B is [K,N] row-major.  TRANSB=true: B is [N,K] row-major (C=A·B^T).
// 128x128 block tile, BK=16, 256 thr = 8 warps (4x2), warp tile 32x64 (m16n8k8).
// Requires M%128==N%128==0, K%16==0.
template <bool TRANSB, int ACT, bool RES>
__global__ __launch_bounds__(256) void gemm_tc(
    const float* __restrict__ A, const float* __restrict__ B,
    const float* __restrict__ bias, const float* __restrict__ res,
    float* __restrict__ C, int M, int N, int K) {
    __shared__ unsigned As[128][17];   // [m][k] + pad
    __shared__ unsigned Bs[16][132];   // [k][n] + pad
    const int tid  = threadIdx.x;
    const int lane = tid & 31, warp = tid >> 5;
    const int wm = warp >> 1, wn = warp & 1;          // 4 x 2 warps
    const int m0 = blockIdx.y * 128, n0 = blockIdx.x * 128;

    float acc[2][8][4];
    #pragma unroll
    for (int i = 0; i < 2; i++)
        #pragma unroll
        for (int j = 0; j < 8; j++)
            #pragma unroll
            for (int q = 0; q < 4; q++) acc[i][j][q] = 0.0f;

    const int arow = tid >> 1, akoff = (tid & 1) * 8;     // A: 128 rows x 16 k
    const int brow = tid >> 4, bnoff = (tid & 15) * 8;    // B (KxN): 16 rows x 128 n
    const int tbn  = tid >> 1, tbk   = (tid & 1) * 8;     // B^T (NxK): 128 n x 16 k

    float4 ra0, ra1, rb0, rb1;
    auto loadg = [&](int k0) {
        const float* ap = A + (size_t)(m0 + arow) * K + k0 + akoff;
        ra0 = *(const float4*)ap; ra1 = *(const float4*)(ap + 4);
        if (!TRANSB) {
            const float* bp = B + (size_t)(k0 + brow) * N + n0 + bnoff;
            rb0 = *(const float4*)bp; rb1 = *(const float4*)(bp + 4);
        } else {
            const float* bp = B + (size_t)(n0 + tbn) * K + k0 + tbk;
            rb0 = *(const float4*)bp; rb1 = *(const float4*)(bp + 4);
        }
    };
    auto stores = [&]() {
        unsigned* a = &As[arow][akoff];
        a[0] = f2t(ra0.x); a[1] = f2t(ra0.y); a[2] = f2t(ra0.z); a[3] = f2t(ra0.w);
        a[4] = f2t(ra1.x); a[5] = f2t(ra1.y); a[6] = f2t(ra1.z); a[7] = f2t(ra1.w);
        if (!TRANSB) {
            unsigned* b = &Bs[brow][bnoff];
            b[0] = f2t(rb0.x); b[1] = f2t(rb0.y); b[2] = f2t(rb0.z); b[3] = f2t(rb0.w);
            b[4] = f2t(rb1.x); b[5] = f2t(rb1.y); b[6] = f2t(rb1.z); b[7] = f2t(rb1.w);
        } else {
            Bs[tbk + 0][tbn] = f2t(rb0.x); Bs[tbk + 1][tbn] = f2t(rb0.y);
            Bs[tbk + 2][tbn] = f2t(rb0.z); Bs[tbk + 3][tbn] = f2t(rb0.w);
            Bs[tbk + 4][tbn] = f2t(rb1.x); Bs[tbk + 5][tbn] = f2t(rb1.y);
            Bs[tbk + 6][tbn] = f2t(rb1.z); Bs[tbk + 7][tbn] = f2t(rb1.w);
        }
    };

    loadg(0);
    stores();
    __syncthreads();

    for (int k0 = 0; k0 < K; k0 += 16) {
        bool more = (k0 + 16) < K;
        if (more) loadg(k0 + 16);

        #pragma unroll
        for (int ks = 0; ks < 2; ks++) {
            const int kb = ks * 8;
            unsigned af[2][4], bf[8][2];
            #pragma unroll
            for (int mt = 0; mt < 2; mt++) {
                int m = wm * 32 + mt * 16 + (lane >> 2);
                int k = kb + (lane & 3);
                af[mt][0] = As[m    ][k    ];
                af[mt][1] = As[m + 8][k    ];
                af[mt][2] = As[m    ][k + 4];
                af[mt][3] = As[m + 8][k + 4];
            }
            #pragma unroll
            for (int nt = 0; nt < 8; nt++) {
                int n = wn * 64 + nt * 8 + (lane >> 2);
                int k = kb + (lane & 3);
                bf[nt][0] = Bs[k    ][n];
                bf[nt][1] = Bs[k + 4][n];
            }
            #pragma unroll
            for (int mt = 0; mt < 2; mt++)
                #pragma unroll
                for (int nt = 0; nt < 8; nt++)
                    mma_tf32(acc[mt][nt], af[mt], bf[nt]);
        }
        __syncthreads();
        if (more) {
            stores();
            __syncthreads();
        }
    }

    // epilogue
    #pragma unroll
    for (int mt = 0; mt < 2; mt++) {
        int r0 = m0 + wm * 32 + mt * 16 + (lane >> 2);
        #pragma unroll
        for (int nt = 0; nt < 8; nt++) {
            int c0i = n0 + wn * 64 + nt * 8 + 2 * (lane & 3);
            #pragma unroll
            for (int half = 0; half < 2; half++) {
                int r = r0 + half * 8;
                float v0 = acc[mt][nt][half * 2 + 0];
                float v1 = acc[mt][nt][half * 2 + 1];
                if (bias) { v0 += bias[c0i]; v1 += bias[c0i + 1]; }
                if (ACT == 1) {
                    v0 = v0 * (1.0f / (1.0f + __expf(-v0)));
                    v1 = v1 * (1.0f / (1.0f + __expf(-v1)));
                }
                if (RES) {
                    const float* rp = res + (size_t)r * N + c0i;
                    v0 += rp[0]; v1 += rp[1];
                }
                float2* cp = (float2*)(C + (size_t)r * N + c0i);
                *cp = make_float2(v0, v1);
            }
        }
    }
}

// ---------------- attention: one block (128 thr) per (b, h, query) ----------------
__global__ void attn_k(const float* __restrict__ qkv, float* __restrict__ out) {
    int t = blockIdx.x, h = blockIdx.y, b = blockIdx.z;
    int row = b * Tv + t;
    __shared__ float qs[64];
    __shared__ float sc[128];
    __shared__ float red[4];
    int tid = threadIdx.x; // 128
    if (tid < 64) qs[tid] = qkv[(size_t)row * QKVN + h * HDv + tid] * 0.125f; // 1/sqrt(64)
    __syncthreads();
    float m = -1e30f, l = 0.0f, acc = 0.0f;
    const float* kbase = qkv + (size_t)(b * Tv) * QKVN + Hv * HDv     + h * HDv;
    const float* vbase = qkv + (size_t)(b * Tv) * QKVN + 2 * Hv * HDv + h * HDv;
    for (int c0 = 0; c0 <= t; c0 += 128) {
        int Lc = min(128, t + 1 - c0);
        float s = -1e30f;
        if (tid < Lc) {
            const float* kp = kbase + (size_t)(c0 + tid) * QKVN;
            float a0 = 0, a1 = 0, a2 = 0, a3 = 0;
            #pragma unroll
            for (int d = 0; d < 64; d += 4) {
                float4 k4 = *(const float4*)(kp + d);
                a0 = fmaf(qs[d    ], k4.x, a0);
                a1 = fmaf(qs[d + 1], k4.y, a1);
                a2 = fmaf(qs[d + 2], k4.z, a2);
                a3 = fmaf(qs[d + 3], k4.w, a3);
            }
            s = a0 + a1 + a2 + a3;
        }
        float wmax = s;
        #pragma unroll
        for (int o = 16; o; o >>= 1) wmax = fmaxf(wmax, __shfl_xor_sync(0xffffffffu, wmax, o));
        if ((tid & 31) == 0) red[tid >> 5] = wmax;
        __syncthreads();
        float m_new = fmaxf(fmaxf(red[0], red[1]), fmaxf(red[2], red[3]));
        m_new = fmaxf(m, m_new);
        float p = (tid < Lc) ? __expf(s - m_new) : 0.0f;
        sc[tid] = p;
        float ws = p;
        #pragma unroll
        for (int o = 16; o; o >>= 1) ws += __shfl_xor_sync(0xffffffffu, ws, o);
        __syncthreads();
        if ((tid & 31) == 0) red[tid >> 5] = ws;
        __syncthreads();
        float csum = red[0] + red[1] + red[2] + red[3];
        float scale = __expf(m - m_new);
        l = l * scale + csum;
        m = m_new;
        if (tid < 64) {
            const float* vp = vbase + (size_t)c0 * QKVN + tid;
            float a2 = acc * scale;
            #pragma unroll 4
            for (int j = 0; j < Lc; j++) a2 = fmaf(sc[j], vp[(size_t)j * QKVN], a2);
            acc = a2;
        }
        __syncthreads();
    }
    if (tid < 64) out[(size_t)row * Dv + h * HDv + tid] = acc / l;
}

// ---------------- driver ----------------
extern "C" void kernel_launch(void* const* d_in, const int* in_sizes, int n_in,
                              void* d_out, int out_size) {
    const int*   ids   = (const int*)  d_in[0];
    const float* te    = (const float*)d_in[1];
    const float* pe    = (const float*)d_in[2];
    const float* ln1_s = (const float*)d_in[3];
    const float* ln1_b = (const float*)d_in[4];
    const float* qkv_w = (const float*)d_in[5];
    const float* qkv_b = (const float*)d_in[6];
    const float* out_w = (const float*)d_in[7];
    const float* out_b = (const float*)d_in[8];
    const float* ln2_s = (const float*)d_in[9];
    const float* ln2_b = (const float*)d_in[10];
    const float* up_w  = (const float*)d_in[11];
    const float* up_b  = (const float*)d_in[12];
    const float* dn_w  = (const float*)d_in[13];
    const float* dn_b  = (const float*)d_in[14];
    const float* lnf_s = (const float*)d_in[15];
    const float* lnf_b = (const float*)d_in[16];
    float* logits = (float*)d_out;

    float *x, *lnb, *qkv, *att, *ff;
    cudaGetSymbolAddress((void**)&x,   g_x);
    cudaGetSymbolAddress((void**)&lnb, g_ln);
    cudaGetSymbolAddress((void**)&qkv, g_qkv);
    cudaGetSymbolAddress((void**)&att, g_att);
    cudaGetSymbolAddress((void**)&ff,  g_ff);

    embed_k<<<(Mv * Dv + 255) / 256, 256>>>(ids, te, pe, x);

    for (int i = 0; i < Lv; i++) {
        ln_k<<<Mv, 256>>>(x, ln1_s + (size_t)i * Dv, ln1_b + (size_t)i * Dv, lnb);
        gemm_tc<false, 0, false><<<dim3(QKVN / 128, Mv / 128), 256>>>(
            lnb, qkv_w + (size_t)i * Dv * QKVN, qkv_b + (size_t)i * QKVN,
            nullptr, qkv, Mv, QKVN, Dv);
        attn_k<<<dim3(Tv, Hv, Bv), 128>>>(qkv, att);
        gemm_tc<false, 0, true><<<dim3(Dv / 128, Mv / 128), 256>>>(
            att, out_w + (size_t)i * Dv * Dv, out_b + (size_t)i * Dv,
            x, x, Mv, Dv, Dv);
        ln_k<<<Mv, 256>>>(x, ln2_s + (size_t)i * Dv, ln2_b + (size_t)i * Dv, lnb);
        gemm_tc<false, 1, false><<<dim3(DFv / 128, Mv / 128), 256>>>(
            lnb, up_w + (size_t)i * Dv * DFv, up_b + (size_t)i * DFv,
            nullptr, ff, Mv, DFv, Dv);
        gemm_tc<false, 0, true><<<dim3(Dv / 128, Mv / 128), 256>>>(
            ff, dn_w + (size_t)i * DFv * Dv, dn_b + (size_t)i * Dv,
            x, x, Mv, Dv, DFv);
    }

    ln_k<<<Mv, 256>>>(x, lnf_s, lnf_b, lnb);
    // logits = lnf(x) @ te^T   (tied head, no bias)
    gemm_tc<true, 0, false><<<dim3(Vv / 128, Mv / 128), 256>>>(
        lnb, te, nullptr, nullptr, logits, Mv, Vv, Dv);
}

// round 3
// speedup vs baseline: 4.2579x; 3.2227x over previous
#include <cuda_runtime.h>
#include <math.h>

#define Bv   2
#define Tv   2048
#define Dv   768
#define Hv   12
#define HDv  64
#define Lv   4
#define DFv  3072
#define Vv   32000
#define Mv   (Bv*Tv)        /* 4096 rows */
#define QKVN (3*Hv*HDv)     /* 2304 */

// ---------------- scratch (static device globals; no allocs) ----------------
__device__ float g_x  [Mv*Dv];     // residual stream
__device__ float g_ln [Mv*Dv];     // layernorm output
__device__ float g_qkv[Mv*QKVN];   // qkv projection
__device__ float g_att[Mv*Dv];     // attention output
__device__ float g_ff [Mv*DFv];    // ffn hidden

// ---------------- embedding ----------------
__global__ void embed_k(const int* __restrict__ ids, const float* __restrict__ te,
                        const float* __restrict__ pe, float* __restrict__ x) {
    int i = blockIdx.x * blockDim.x + threadIdx.x;
    if (i >= Mv * Dv) return;
    int r = i / Dv, d = i - r * Dv;
    int t = r % Tv;
    x[i] = te[(size_t)ids[r] * Dv + d] + pe[(size_t)t * Dv + d];
}

// ---------------- layernorm: one block (256 thr) per row of 768 ----------------
__global__ void ln_k(const float* __restrict__ x, const float* __restrict__ s,
                     const float* __restrict__ bb, float* __restrict__ y) {
    int r = blockIdx.x;
    const float* xr = x + (size_t)r * Dv;
    float*       yr = y + (size_t)r * Dv;
    __shared__ float red[8];
    int tid = threadIdx.x; // 256
    float v0 = xr[tid], v1 = xr[tid + 256], v2 = xr[tid + 512];
    float sum = v0 + v1 + v2;
    #pragma unroll
    for (int o = 16; o; o >>= 1) sum += __shfl_xor_sync(0xffffffffu, sum, o);
    if ((tid & 31) == 0) red[tid >> 5] = sum;
    __syncthreads();
    float mu = (red[0]+red[1]+red[2]+red[3]+red[4]+red[5]+red[6]+red[7]) * (1.0f/Dv);
    float d0 = v0 - mu, d1 = v1 - mu, d2 = v2 - mu;
    float sq = d0*d0 + d1*d1 + d2*d2;
    __syncthreads();
    #pragma unroll
    for (int o = 16; o; o >>= 1) sq += __shfl_xor_sync(0xffffffffu, sq, o);
    if ((tid & 31) == 0) red[tid >> 5] = sq;
    __syncthreads();
    float var = (red[0]+red[1]+red[2]+red[3]+red[4]+red[5]+red[6]+red[7]) * (1.0f/Dv);
    float rstd = rsqrtf(var + 1e-5f);
    yr[tid      ] = d0 * rstd * s[tid      ] + bb[tid      ];
    yr[tid + 256] = d1 * rstd * s[tid + 256] + bb[tid + 256];
    yr[tid + 512] = d2 * rstd * s[tid + 512] + bb[tid + 512];
}

// ---------------- TF32 helpers ----------------
__device__ __forceinline__ unsigned f2t(float f) {
    unsigned u; asm("cvt.rna.tf32.f32 %0, %1;" : "=r"(u) : "f"(f)); return u;
}
__device__ __forceinline__ void mma_tf32(float* c, const unsigned* a, const unsigned* b) {
    asm volatile(
        "mma.sync.aligned.m16n8k8.row.col.f32.tf32.tf32.f32 "
        "{%0,%1,%2,%3}, {%4,%5,%6,%7}, {%8,%9}, {%0,%1,%2,%3};\n"
        : "+f"(c[0]), "+f"(c[1]), "+f"(c[2]), "+f"(c[3])
        : "r"(a[0]), "r"(a[1]), "r"(a[2]), "r"(a[3]), "r"(b[0]), "r"(b[1]));
}

// ---------------- Tensor-core GEMM: C[M,N] = A[M,K] @ B (+bias)(+silu)(+res) ----
template <bool TRANSB, int ACT, bool RES>
__global__ __launch_bounds__(256) void gemm_tc(
    const float* __restrict__ A, const float* __restrict__ B,
    const float* __restrict__ bias, const float* __restrict__ res,
    float* __restrict__ C, int M, int N, int K) {
    __shared__ unsigned As[128][17];   // [m][k] + pad
    __shared__ unsigned Bs[16][132];   // [k][n] + pad
    const int tid  = threadIdx.x;
    const int lane = tid & 31, warp = tid >> 5;
    const int wm = warp >> 1, wn = warp & 1;          // 4 x 2 warps
    const int m0 = blockIdx.y * 128, n0 = blockIdx.x * 128;

    float acc[2][8][4];
    #pragma unroll
    for (int i = 0; i < 2; i++)
        #pragma unroll
        for (int j = 0; j < 8; j++)
            #pragma unroll
            for (int q = 0; q < 4; q++) acc[i][j][q] = 0.0f;

    const int arow = tid >> 1, akoff = (tid & 1) * 8;
    const int brow = tid >> 4, bnoff = (tid & 15) * 8;
    const int tbn  = tid >> 1, tbk   = (tid & 1) * 8;

    float4 ra0, ra1, rb0, rb1;
    auto loadg = [&](int k0) {
        const float* ap = A + (size_t)(m0 + arow) * K + k0 + akoff;
        ra0 = *(const float4*)ap; ra1 = *(const float4*)(ap + 4);
        if (!TRANSB) {
            const float* bp = B + (size_t)(k0 + brow) * N + n0 + bnoff;
            rb0 = *(const float4*)bp; rb1 = *(const float4*)(bp + 4);
        } else {
            const float* bp = B + (size_t)(n0 + tbn) * K + k0 + tbk;
            rb0 = *(const float4*)bp; rb1 = *(const float4*)(bp + 4);
        }
    };
    auto stores = [&]() {
        unsigned* a = &As[arow][akoff];
        a[0] = f2t(ra0.x); a[1] = f2t(ra0.y); a[2] = f2t(ra0.z); a[3] = f2t(ra0.w);
        a[4] = f2t(ra1.x); a[5] = f2t(ra1.y); a[6] = f2t(ra1.z); a[7] = f2t(ra1.w);
        if (!TRANSB) {
            unsigned* b = &Bs[brow][bnoff];
            b[0] = f2t(rb0.x); b[1] = f2t(rb0.y); b[2] = f2t(rb0.z); b[3] = f2t(rb0.w);
            b[4] = f2t(rb1.x); b[5] = f2t(rb1.y); b[6] = f2t(rb1.z); b[7] = f2t(rb1.w);
        } else {
            Bs[tbk + 0][tbn] = f2t(rb0.x); Bs[tbk + 1][tbn] = f2t(rb0.y);
            Bs[tbk + 2][tbn] = f2t(rb0.z); Bs[tbk + 3][tbn] = f2t(rb0.w);
            Bs[tbk + 4][tbn] = f2t(rb1.x); Bs[tbk + 5][tbn] = f2t(rb1.y);
            Bs[tbk + 6][tbn] = f2t(rb1.z); Bs[tbk + 7][tbn] = f2t(rb1.w);
        }
    };

    loadg(0);
    stores();
    __syncthreads();

    for (int k0 = 0; k0 < K; k0 += 16) {
        bool more = (k0 + 16) < K;
        if (more) loadg(k0 + 16);

        #pragma unroll
        for (int ks = 0; ks < 2; ks++) {
            const int kb = ks * 8;
            unsigned af[2][4], bf[8][2];
            #pragma unroll
            for (int mt = 0; mt < 2; mt++) {
                int m = wm * 32 + mt * 16 + (lane >> 2);
                int k = kb + (lane & 3);
                af[mt][0] = As[m    ][k    ];
                af[mt][1] = As[m + 8][k    ];
                af[mt][2] = As[m    ][k + 4];
                af[mt][3] = As[m + 8][k + 4];
            }
            #pragma unroll
            for (int nt = 0; nt < 8; nt++) {
                int n = wn * 64 + nt * 8 + (lane >> 2);
                int k = kb + (lane & 3);
                bf[nt][0] = Bs[k    ][n];
                bf[nt][1] = Bs[k + 4][n];
            }
            #pragma unroll
            for (int mt = 0; mt < 2; mt++)
                #pragma unroll
                for (int nt = 0; nt < 8; nt++)
                    mma_tf32(acc[mt][nt], af[mt], bf[nt]);
        }
        __syncthreads();
        if (more) {
            stores();
            __syncthreads();
        }
    }

    #pragma unroll
    for (int mt = 0; mt < 2; mt++) {
        int r0 = m0 + wm * 32 + mt * 16 + (lane >> 2);
        #pragma unroll
        for (int nt = 0; nt < 8; nt++) {
            int c0i = n0 + wn * 64 + nt * 8 + 2 * (lane & 3);
            #pragma unroll
            for (int half = 0; half < 2; half++) {
                int r = r0 + half * 8;
                float v0 = acc[mt][nt][half * 2 + 0];
                float v1 = acc[mt][nt][half * 2 + 1];
                if (bias) { v0 += bias[c0i]; v1 += bias[c0i + 1]; }
                if (ACT == 1) {
                    v0 = v0 * (1.0f / (1.0f + __expf(-v0)));
                    v1 = v1 * (1.0f / (1.0f + __expf(-v1)));
                }
                if (RES) {
                    const float* rp = res + (size_t)r * N + c0i;
                    v0 += rp[0]; v1 += rp[1];
                }
                float2* cp = (float2*)(C + (size_t)r * N + c0i);
                *cp = make_float2(v0, v1);
            }
        }
    }
}

// ---------------- flash attention: 64 queries x one (b,h) per block ------------
// 256 threads = 8 warps in 4x2. TF32 mma for S=Q.K^T and O+=P.V.
// Dynamic SMEM layout (unsigned/float, all 4B):
//   Qs [64][68] tf32, Ks [64][68] tf32, Vs [64][72] tf32, Ss [64][68] f32/tf32,
//   m[64], l[64], sc[64]
#define QPAD 68
#define VPAD 72
#define ATTN_SMEM ((64*QPAD + 64*QPAD + 64*VPAD + 64*QPAD + 3*64) * 4)

__global__ __launch_bounds__(256) void attn_flash_k(
    const float* __restrict__ qkv, float* __restrict__ out) {
    extern __shared__ unsigned smem[];
    unsigned* Qs = smem;                       // [64][QPAD]
    unsigned* Ks = Qs + 64 * QPAD;             // [64][QPAD]
    unsigned* Vs = Ks + 64 * QPAD;             // [64][VPAD]
    float*    Ss = (float*)(Vs + 64 * VPAD);   // [64][QPAD]
    float*    m_sm = Ss + 64 * QPAD;           // [64]
    float*    l_sm = m_sm + 64;                // [64]
    float*    sc_sm = l_sm + 64;               // [64]

    const int q0 = blockIdx.x * 64;
    const int h  = blockIdx.y;
    const int b  = blockIdx.z;
    const int tid = threadIdx.x;
    const int lane = tid & 31, warp = tid >> 5;
    const int wm = warp >> 1, wn = warp & 1;   // 4 x 2

    const float* qbase = qkv + (size_t)(b * Tv) * QKVN + h * HDv;
    const float* kbase = qbase + Hv * HDv;
    const float* vbase = qbase + 2 * Hv * HDv;

    // load Q tile (64 rows x 64 cols), pre-scaled by 1/sqrt(64)
    #pragma unroll
    for (int it = 0; it < 4; it++) {
        int e = tid + 256 * it;              // float4 index over 1024
        int r = e >> 4, d = (e & 15) * 4;
        float4 q4 = *(const float4*)(qbase + (size_t)(q0 + r) * QKVN + d);
        unsigned* dst = Qs + r * QPAD + d;
        dst[0] = f2t(q4.x * 0.125f); dst[1] = f2t(q4.y * 0.125f);
        dst[2] = f2t(q4.z * 0.125f); dst[3] = f2t(q4.w * 0.125f);
    }
    if (tid < 64) { m_sm[tid] = -1e30f; l_sm[tid] = 0.0f; }

    float acc_o[4][4];
    #pragma unroll
    for (int i = 0; i < 4; i++)
        #pragma unroll
        for (int j = 0; j < 4; j++) acc_o[i][j] = 0.0f;

    for (int c0 = 0; c0 <= q0; c0 += 64) {
        // ---- load K, V chunk ----
        #pragma unroll
        for (int it = 0; it < 4; it++) {
            int e = tid + 256 * it;
            int r = e >> 4, d = (e & 15) * 4;
            float4 k4 = *(const float4*)(kbase + (size_t)(c0 + r) * QKVN + d);
            unsigned* kd = Ks + r * QPAD + d;
            kd[0] = f2t(k4.x); kd[1] = f2t(k4.y); kd[2] = f2t(k4.z); kd[3] = f2t(k4.w);
            float4 v4 = *(const float4*)(vbase + (size_t)(c0 + r) * QKVN + d);
            unsigned* vd = Vs + r * VPAD + d;
            vd[0] = f2t(v4.x); vd[1] = f2t(v4.y); vd[2] = f2t(v4.z); vd[3] = f2t(v4.w);
        }
        __syncthreads();

        // ---- S = Q . K^T   (warp tile 16x32) ----
        float s_acc[4][4];
        #pragma unroll
        for (int i = 0; i < 4; i++)
            #pragma unroll
            for (int j = 0; j < 4; j++) s_acc[i][j] = 0.0f;
        #pragma unroll
        for (int kb = 0; kb < 64; kb += 8) {
            unsigned af[4], bf[4][2];
            int mr = wm * 16 + (lane >> 2);
            int kk = kb + (lane & 3);
            af[0] = Qs[mr * QPAD + kk];
            af[1] = Qs[(mr + 8) * QPAD + kk];
            af[2] = Qs[mr * QPAD + kk + 4];
            af[3] = Qs[(mr + 8) * QPAD + kk + 4];
            #pragma unroll
            for (int nt = 0; nt < 4; nt++) {
                int n = wn * 32 + nt * 8 + (lane >> 2);
                bf[nt][0] = Ks[n * QPAD + kb + (lane & 3)];
                bf[nt][1] = Ks[n * QPAD + kb + (lane & 3) + 4];
            }
            #pragma unroll
            for (int nt = 0; nt < 4; nt++)
                mma_tf32(s_acc[nt], af, bf[nt]);
        }
        // store S to SMEM (+ causal mask on diagonal chunk)
        const bool diag = (c0 == q0);
        #pragma unroll
        for (int nt = 0; nt < 4; nt++) {
            int c = wn * 32 + nt * 8 + 2 * (lane & 3);
            #pragma unroll
            for (int half = 0; half < 2; half++) {
                int r = wm * 16 + (lane >> 2) + half * 8;
                float v0 = s_acc[nt][half * 2 + 0];
                float v1 = s_acc[nt][half * 2 + 1];
                if (diag) {
                    if (c     > r) v0 = -1e30f;
                    if (c + 1 > r) v1 = -1e30f;
                }
                Ss[r * QPAD + c] = v0; Ss[r * QPAD + c + 1] = v1;
            }
        }
        __syncthreads();

        // ---- online softmax: 4 threads per row ----
        {
            int r = tid >> 2, g = tid & 3;
            float* row = Ss + r * QPAD;
            float cmax = -1e30f;
            #pragma unroll
            for (int j = 0; j < 16; j++) cmax = fmaxf(cmax, row[g + 4 * j]);
            cmax = fmaxf(cmax, __shfl_xor_sync(0xffffffffu, cmax, 1));
            cmax = fmaxf(cmax, __shfl_xor_sync(0xffffffffu, cmax, 2));
            float m_old = m_sm[r];
            float m_new = fmaxf(m_old, cmax);
            float csum = 0.0f;
            unsigned* prow = (unsigned*)row;
            #pragma unroll
            for (int j = 0; j < 16; j++) {
                float p = __expf(row[g + 4 * j] - m_new);
                csum += p;
                prow[g + 4 * j] = f2t(p);
            }
            csum += __shfl_xor_sync(0xffffffffu, csum, 1);
            csum += __shfl_xor_sync(0xffffffffu, csum, 2);
            if (g == 0) {
                float scale = __expf(m_old - m_new);
                sc_sm[r] = scale;
                l_sm[r] = l_sm[r] * scale + csum;
                m_sm[r] = m_new;
            }
        }
        __syncthreads();

        // ---- rescale O, then O += P . V ----
        {
            int r1 = wm * 16 + (lane >> 2);
            float s1 = sc_sm[r1], s2 = sc_sm[r1 + 8];
            #pragma unroll
            for (int nt = 0; nt < 4; nt++) {
                acc_o[nt][0] *= s1; acc_o[nt][1] *= s1;
                acc_o[nt][2] *= s2; acc_o[nt][3] *= s2;
            }
        }
        const unsigned* Pu = (const unsigned*)Ss;
        #pragma unroll
        for (int kb = 0; kb < 64; kb += 8) {
            unsigned af[4], bf[4][2];
            int mr = wm * 16 + (lane >> 2);
            int kk = kb + (lane & 3);
            af[0] = Pu[mr * QPAD + kk];
            af[1] = Pu[(mr + 8) * QPAD + kk];
            af[2] = Pu[mr * QPAD + kk + 4];
            af[3] = Pu[(mr + 8) * QPAD + kk + 4];
            #pragma unroll
            for (int nt = 0; nt < 4; nt++) {
                int n = wn * 32 + nt * 8 + (lane >> 2);
                bf[nt][0] = Vs[(kb + (lane & 3)) * VPAD + n];
                bf[nt][1] = Vs[(kb + (lane & 3) + 4) * VPAD + n];
            }
            #pragma unroll
            for (int nt = 0; nt < 4; nt++)
                mma_tf32(acc_o[nt], af, bf[nt]);
        }
        __syncthreads();   // protect Ks/Vs/Ss before next chunk
    }

    // ---- output: O / l ----
    {
        int r1 = wm * 16 + (lane >> 2);
        float inv1 = 1.0f / l_sm[r1], inv2 = 1.0f / l_sm[r1 + 8];
        #pragma unroll
        for (int nt = 0; nt < 4; nt++) {
            int c = wn * 32 + nt * 8 + 2 * (lane & 3);
            float* o1 = out + (size_t)(b * Tv + q0 + r1) * Dv + h * HDv + c;
            float* o2 = out + (size_t)(b * Tv + q0 + r1 + 8) * Dv + h * HDv + c;
            o1[0] = acc_o[nt][0] * inv1; o1[1] = acc_o[nt][1] * inv1;
            o2[0] = acc_o[nt][2] * inv2; o2[1] = acc_o[nt][3] * inv2;
        }
    }
}

// ---------------- driver ----------------
extern "C" void kernel_launch(void* const* d_in, const int* in_sizes, int n_in,
                              void* d_out, int out_size) {
    const int*   ids   = (const int*)  d_in[0];
    const float* te    = (const float*)d_in[1];
    const float* pe    = (const float*)d_in[2];
    const float* ln1_s = (const float*)d_in[3];
    const float* ln1_b = (const float*)d_in[4];
    const float* qkv_w = (const float*)d_in[5];
    const float* qkv_b = (const float*)d_in[6];
    const float* out_w = (const float*)d_in[7];
    const float* out_b = (const float*)d_in[8];
    const float* ln2_s = (const float*)d_in[9];
    const float* ln2_b = (const float*)d_in[10];
    const float* up_w  = (const float*)d_in[11];
    const float* up_b  = (const float*)d_in[12];
    const float* dn_w  = (const float*)d_in[13];
    const float* dn_b  = (const float*)d_in[14];
    const float* lnf_s = (const float*)d_in[15];
    const float* lnf_b = (const float*)d_in[16];
    float* logits = (float*)d_out;

    float *x, *lnb, *qkv, *att, *ff;
    cudaGetSymbolAddress((void**)&x,   g_x);
    cudaGetSymbolAddress((void**)&lnb, g_ln);
    cudaGetSymbolAddress((void**)&qkv, g_qkv);
    cudaGetSymbolAddress((void**)&att, g_att);
    cudaGetSymbolAddress((void**)&ff,  g_ff);

    cudaFuncSetAttribute(attn_flash_k,
                         cudaFuncAttributeMaxDynamicSharedMemorySize, ATTN_SMEM);

    embed_k<<<(Mv * Dv + 255) / 256, 256>>>(ids, te, pe, x);

    for (int i = 0; i < Lv; i++) {
        ln_k<<<Mv, 256>>>(x, ln1_s + (size_t)i * Dv, ln1_b + (size_t)i * Dv, lnb);
        gemm_tc<false, 0, false><<<dim3(QKVN / 128, Mv / 128), 256>>>(
            lnb, qkv_w + (size_t)i * Dv * QKVN, qkv_b + (size_t)i * QKVN,
            nullptr, qkv, Mv, QKVN, Dv);
        attn_flash_k<<<dim3(Tv / 64, Hv, Bv), 256, ATTN_SMEM>>>(qkv, att);
        gemm_tc<false, 0, true><<<dim3(Dv / 128, Mv / 128), 256>>>(
            att, out_w + (size_t)i * Dv * Dv, out_b + (size_t)i * Dv,
            x, x, Mv, Dv, Dv);
        ln_k<<<Mv, 256>>>(x, ln2_s + (size_t)i * Dv, ln2_b + (size_t)i * Dv, lnb);
        gemm_tc<false, 1, false><<<dim3(DFv / 128, Mv / 128), 256>>>(
            lnb, up_w + (size_t)i * Dv * DFv, up_b + (size_t)i * DFv,
            nullptr, ff, Mv, DFv, Dv);
        gemm_tc<false, 0, true><<<dim3(Dv / 128, Mv / 128), 256>>>(
            ff, dn_w + (size_t)i * DFv * Dv, dn_b + (size_t)i * Dv,
            x, x, Mv, Dv, DFv);
    }

    ln_k<<<Mv, 256>>>(x, lnf_s, lnf_b, lnb);
    gemm_tc<true, 0, false><<<dim3(Vv / 128, Mv / 128), 256>>>(
        lnb, te, nullptr, nullptr, logits, Mv, Vv, Dv);
}

// round 4
// speedup vs baseline: 4.9825x; 1.1702x over previous
#include <cuda_runtime.h>
#include <math.h>

#define Bv   2
#define Tv   2048
#define Dv   768
#define Hv   12
#define HDv  64
#define Lv   4
#define DFv  3072
#define Vv   32000
#define Mv   (Bv*Tv)        /* 4096 rows */
#define QKVN (3*Hv*HDv)     /* 2304 */

// ---------------- scratch (static device globals; no allocs) ----------------
__device__ float g_x  [Mv*Dv];     // residual stream
__device__ float g_ln [Mv*Dv];     // layernorm output
__device__ float g_qkv[Mv*QKVN];   // qkv projection
__device__ float g_att[Mv*Dv];     // attention output
__device__ float g_ff [Mv*DFv];    // ffn hidden

// ---------------- embedding ----------------
__global__ void embed_k(const int* __restrict__ ids, const float* __restrict__ te,
                        const float* __restrict__ pe, float* __restrict__ x) {
    int i = blockIdx.x * blockDim.x + threadIdx.x;
    if (i >= Mv * Dv) return;
    int r = i / Dv, d = i - r * Dv;
    int t = r % Tv;
    x[i] = te[(size_t)ids[r] * Dv + d] + pe[(size_t)t * Dv + d];
}

// ---------------- layernorm: one block (256 thr) per row of 768 ----------------
__global__ void ln_k(const float* __restrict__ x, const float* __restrict__ s,
                     const float* __restrict__ bb, float* __restrict__ y) {
    int r = blockIdx.x;
    const float* xr = x + (size_t)r * Dv;
    float*       yr = y + (size_t)r * Dv;
    __shared__ float red[8];
    int tid = threadIdx.x; // 256
    float v0 = xr[tid], v1 = xr[tid + 256], v2 = xr[tid + 512];
    float sum = v0 + v1 + v2;
    #pragma unroll
    for (int o = 16; o; o >>= 1) sum += __shfl_xor_sync(0xffffffffu, sum, o);
    if ((tid & 31) == 0) red[tid >> 5] = sum;
    __syncthreads();
    float mu = (red[0]+red[1]+red[2]+red[3]+red[4]+red[5]+red[6]+red[7]) * (1.0f/Dv);
    float d0 = v0 - mu, d1 = v1 - mu, d2 = v2 - mu;
    float sq = d0*d0 + d1*d1 + d2*d2;
    __syncthreads();
    #pragma unroll
    for (int o = 16; o; o >>= 1) sq += __shfl_xor_sync(0xffffffffu, sq, o);
    if ((tid & 31) == 0) red[tid >> 5] = sq;
    __syncthreads();
    float var = (red[0]+red[1]+red[2]+red[3]+red[4]+red[5]+red[6]+red[7]) * (1.0f/Dv);
    float rstd = rsqrtf(var + 1e-5f);
    yr[tid      ] = d0 * rstd * s[tid      ] + bb[tid      ];
    yr[tid + 256] = d1 * rstd * s[tid + 256] + bb[tid + 256];
    yr[tid + 512] = d2 * rstd * s[tid + 512] + bb[tid + 512];
}

// ---------------- TF32 helpers ----------------
__device__ __forceinline__ unsigned f2t(float f) {
    unsigned u; asm("cvt.rna.tf32.f32 %0, %1;" : "=r"(u) : "f"(f)); return u;
}
__device__ __forceinline__ void mma_tf32(float* c, const unsigned* a, const unsigned* b) {
    asm volatile(
        "mma.sync.aligned.m16n8k8.row.col.f32.tf32.tf32.f32 "
        "{%0,%1,%2,%3}, {%4,%5,%6,%7}, {%8,%9}, {%0,%1,%2,%3};\n"
        : "+f"(c[0]), "+f"(c[1]), "+f"(c[2]), "+f"(c[3])
        : "r"(a[0]), "r"(a[1]), "r"(a[2]), "r"(a[3]), "r"(b[0]), "r"(b[1]));
}

// ---------------- Tensor-core GEMM: C[M,N] = A[M,K] @ B (+bias)(+silu)(+res) ----
// Double-buffered SMEM, conflict-free pads, vectorized staging stores.
// 128x128 tile, BK=16, 256 thr = 8 warps (4x2), warp tile 32x64 (m16n8k8).
#define APAD 20    /* stride 20 mod 32 -> conflict-free A frag reads, 16B rows */
#define BPAD 136   /* stride 136 mod 32 = 8 -> conflict-free B frag reads */
template <bool TRANSB, int ACT, bool RES>
__global__ __launch_bounds__(256) void gemm_tc(
    const float* __restrict__ A, const float* __restrict__ B,
    const float* __restrict__ bias, const float* __restrict__ res,
    float* __restrict__ C, int M, int N, int K) {
    __shared__ unsigned As[2][128][APAD];
    __shared__ unsigned Bs[2][16][BPAD];
    const int tid  = threadIdx.x;
    const int lane = tid & 31, warp = tid >> 5;
    const int wm = warp >> 1, wn = warp & 1;          // 4 x 2 warps
    const int m0 = blockIdx.y * 128, n0 = blockIdx.x * 128;

    float acc[2][8][4];
    #pragma unroll
    for (int i = 0; i < 2; i++)
        #pragma unroll
        for (int j = 0; j < 8; j++)
            #pragma unroll
            for (int q = 0; q < 4; q++) acc[i][j][q] = 0.0f;

    const int arow = tid >> 1, akoff = (tid & 1) * 8;
    const int brow = tid >> 4, bnoff = (tid & 15) * 8;
    const int tbn  = tid >> 1, tbk   = (tid & 1) * 8;

    float4 ra0, ra1, rb0, rb1;
    auto loadg = [&](int k0) {
        const float* ap = A + (size_t)(m0 + arow) * K + k0 + akoff;
        ra0 = *(const float4*)ap; ra1 = *(const float4*)(ap + 4);
        if (!TRANSB) {
            const float* bp = B + (size_t)(k0 + brow) * N + n0 + bnoff;
            rb0 = *(const float4*)bp; rb1 = *(const float4*)(bp + 4);
        } else {
            const float* bp = B + (size_t)(n0 + tbn) * K + k0 + tbk;
            rb0 = *(const float4*)bp; rb1 = *(const float4*)(bp + 4);
        }
    };
    auto stores = [&](int buf) {
        uint4 av0 = make_uint4(f2t(ra0.x), f2t(ra0.y), f2t(ra0.z), f2t(ra0.w));
        uint4 av1 = make_uint4(f2t(ra1.x), f2t(ra1.y), f2t(ra1.z), f2t(ra1.w));
        uint4* a = (uint4*)&As[buf][arow][akoff];
        a[0] = av0; a[1] = av1;
        if (!TRANSB) {
            uint4 bv0 = make_uint4(f2t(rb0.x), f2t(rb0.y), f2t(rb0.z), f2t(rb0.w));
            uint4 bv1 = make_uint4(f2t(rb1.x), f2t(rb1.y), f2t(rb1.z), f2t(rb1.w));
            uint4* b = (uint4*)&Bs[buf][brow][bnoff];
            b[0] = bv0; b[1] = bv1;
        } else {
            Bs[buf][tbk + 0][tbn] = f2t(rb0.x); Bs[buf][tbk + 1][tbn] = f2t(rb0.y);
            Bs[buf][tbk + 2][tbn] = f2t(rb0.z); Bs[buf][tbk + 3][tbn] = f2t(rb0.w);
            Bs[buf][tbk + 4][tbn] = f2t(rb1.x); Bs[buf][tbk + 5][tbn] = f2t(rb1.y);
            Bs[buf][tbk + 6][tbn] = f2t(rb1.z); Bs[buf][tbk + 7][tbn] = f2t(rb1.w);
        }
    };

    loadg(0);
    stores(0);
    __syncthreads();

    int cur = 0;
    for (int k0 = 0; k0 < K; k0 += 16) {
        bool more = (k0 + 16) < K;
        if (more) loadg(k0 + 16);

        #pragma unroll
        for (int ks = 0; ks < 2; ks++) {
            const int kb = ks * 8;
            unsigned af[2][4], bf[8][2];
            #pragma unroll
            for (int mt = 0; mt < 2; mt++) {
                int m = wm * 32 + mt * 16 + (lane >> 2);
                int k = kb + (lane & 3);
                af[mt][0] = As[cur][m    ][k    ];
                af[mt][1] = As[cur][m + 8][k    ];
                af[mt][2] = As[cur][m    ][k + 4];
                af[mt][3] = As[cur][m + 8][k + 4];
            }
            #pragma unroll
            for (int nt = 0; nt < 8; nt++) {
                int n = wn * 64 + nt * 8 + (lane >> 2);
                int k = kb + (lane & 3);
                bf[nt][0] = Bs[cur][k    ][n];
                bf[nt][1] = Bs[cur][k + 4][n];
            }
            #pragma unroll
            for (int mt = 0; mt < 2; mt++)
                #pragma unroll
                for (int nt = 0; nt < 8; nt++)
                    mma_tf32(acc[mt][nt], af[mt], bf[nt]);
        }
        if (more) {
            stores(cur ^ 1);
            __syncthreads();
            cur ^= 1;
        }
    }

    #pragma unroll
    for (int mt = 0; mt < 2; mt++) {
        int r0 = m0 + wm * 32 + mt * 16 + (lane >> 2);
        #pragma unroll
        for (int nt = 0; nt < 8; nt++) {
            int c0i = n0 + wn * 64 + nt * 8 + 2 * (lane & 3);
            #pragma unroll
            for (int half = 0; half < 2; half++) {
                int r = r0 + half * 8;
                float v0 = acc[mt][nt][half * 2 + 0];
                float v1 = acc[mt][nt][half * 2 + 1];
                if (bias) { v0 += bias[c0i]; v1 += bias[c0i + 1]; }
                if (ACT == 1) {
                    v0 = v0 * (1.0f / (1.0f + __expf(-v0)));
                    v1 = v1 * (1.0f / (1.0f + __expf(-v1)));
                }
                if (RES) {
                    const float* rp = res + (size_t)r * N + c0i;
                    v0 += rp[0]; v1 += rp[1];
                }
                float2* cp = (float2*)(C + (size_t)r * N + c0i);
                *cp = make_float2(v0, v1);
            }
        }
    }
}

// ---------------- flash attention: 64 queries x one (b,h) per block ------------
#define QPAD 68
#define VPAD 72
#define ATTN_SMEM ((64*QPAD + 64*QPAD + 64*VPAD + 64*QPAD + 3*64) * 4)

__global__ __launch_bounds__(256) void attn_flash_k(
    const float* __restrict__ qkv, float* __restrict__ out) {
    extern __shared__ unsigned smem[];
    unsigned* Qs = smem;                       // [64][QPAD]
    unsigned* Ks = Qs + 64 * QPAD;             // [64][QPAD]
    unsigned* Vs = Ks + 64 * QPAD;             // [64][VPAD]
    float*    Ss = (float*)(Vs + 64 * VPAD);   // [64][QPAD]
    float*    m_sm = Ss + 64 * QPAD;           // [64]
    float*    l_sm = m_sm + 64;                // [64]
    float*    sc_sm = l_sm + 64;               // [64]

    const int q0 = blockIdx.x * 64;
    const int h  = blockIdx.y;
    const int b  = blockIdx.z;
    const int tid = threadIdx.x;
    const int lane = tid & 31, warp = tid >> 5;
    const int wm = warp >> 1, wn = warp & 1;   // 4 x 2

    const float* qbase = qkv + (size_t)(b * Tv) * QKVN + h * HDv;
    const float* kbase = qbase + Hv * HDv;
    const float* vbase = qbase + 2 * Hv * HDv;

    #pragma unroll
    for (int it = 0; it < 4; it++) {
        int e = tid + 256 * it;
        int r = e >> 4, d = (e & 15) * 4;
        float4 q4 = *(const float4*)(qbase + (size_t)(q0 + r) * QKVN + d);
        unsigned* dst = Qs + r * QPAD + d;
        dst[0] = f2t(q4.x * 0.125f); dst[1] = f2t(q4.y * 0.125f);
        dst[2] = f2t(q4.z * 0.125f); dst[3] = f2t(q4.w * 0.125f);
    }
    if (tid < 64) { m_sm[tid] = -1e30f; l_sm[tid] = 0.0f; }

    float acc_o[4][4];
    #pragma unroll
    for (int i = 0; i < 4; i++)
        #pragma unroll
        for (int j = 0; j < 4; j++) acc_o[i][j] = 0.0f;

    for (int c0 = 0; c0 <= q0; c0 += 64) {
        #pragma unroll
        for (int it = 0; it < 4; it++) {
            int e = tid + 256 * it;
            int r = e >> 4, d = (e & 15) * 4;
            float4 k4 = *(const float4*)(kbase + (size_t)(c0 + r) * QKVN + d);
            unsigned* kd = Ks + r * QPAD + d;
            kd[0] = f2t(k4.x); kd[1] = f2t(k4.y); kd[2] = f2t(k4.z); kd[3] = f2t(k4.w);
            float4 v4 = *(const float4*)(vbase + (size_t)(c0 + r) * QKVN + d);
            unsigned* vd = Vs + r * VPAD + d;
            vd[0] = f2t(v4.x); vd[1] = f2t(v4.y); vd[2] = f2t(v4.z); vd[3] = f2t(v4.w);
        }
        __syncthreads();

        float s_acc[4][4];
        #pragma unroll
        for (int i = 0; i < 4; i++)
            #pragma unroll
            for (int j = 0; j < 4; j++) s_acc[i][j] = 0.0f;
        #pragma unroll
        for (int kb = 0; kb < 64; kb += 8) {
            unsigned af[4], bf[4][2];
            int mr = wm * 16 + (lane >> 2);
            int kk = kb + (lane & 3);
            af[0] = Qs[mr * QPAD + kk];
            af[1] = Qs[(mr + 8) * QPAD + kk];
            af[2] = Qs[mr * QPAD + kk + 4];
            af[3] = Qs[(mr + 8) * QPAD + kk + 4];
            #pragma unroll
            for (int nt = 0; nt < 4; nt++) {
                int n = wn * 32 + nt * 8 + (lane >> 2);
                bf[nt][0] = Ks[n * QPAD + kb + (lane & 3)];
                bf[nt][1] = Ks[n * QPAD + kb + (lane & 3) + 4];
            }
            #pragma unroll
            for (int nt = 0; nt < 4; nt++)
                mma_tf32(s_acc[nt], af, bf[nt]);
        }
        const bool diag = (c0 == q0);
        #pragma unroll
        for (int nt = 0; nt < 4; nt++) {
            int c = wn * 32 + nt * 8 + 2 * (lane & 3);
            #pragma unroll
            for (int half = 0; half < 2; half++) {
                int r = wm * 16 + (lane >> 2) + half * 8;
                float v0 = s_acc[nt][half * 2 + 0];
                float v1 = s_acc[nt][half * 2 + 1];
                if (diag) {
                    if (c     > r) v0 = -1e30f;
                    if (c + 1 > r) v1 = -1e30f;
                }
                Ss[r * QPAD + c] = v0; Ss[r * QPAD + c + 1] = v1;
            }
        }
        __syncthreads();

        {
            int r = tid >> 2, g = tid & 3;
            float* row = Ss + r * QPAD;
            float cmax = -1e30f;
            #pragma unroll
            for (int j = 0; j < 16; j++) cmax = fmaxf(cmax, row[g + 4 * j]);
            cmax = fmaxf(cmax, __shfl_xor_sync(0xffffffffu, cmax, 1));
            cmax = fmaxf(cmax, __shfl_xor_sync(0xffffffffu, cmax, 2));
            float m_old = m_sm[r];
            float m_new = fmaxf(m_old, cmax);
            float csum = 0.0f;
            unsigned* prow = (unsigned*)row;
            #pragma unroll
            for (int j = 0; j < 16; j++) {
                float p = __expf(row[g + 4 * j] - m_new);
                csum += p;
                prow[g + 4 * j] = f2t(p);
            }
            csum += __shfl_xor_sync(0xffffffffu, csum, 1);
            csum += __shfl_xor_sync(0xffffffffu, csum, 2);
            if (g == 0) {
                float scale = __expf(m_old - m_new);
                sc_sm[r] = scale;
                l_sm[r] = l_sm[r] * scale + csum;
                m_sm[r] = m_new;
            }
        }
        __syncthreads();

        {
            int r1 = wm * 16 + (lane >> 2);
            float s1 = sc_sm[r1], s2 = sc_sm[r1 + 8];
            #pragma unroll
            for (int nt = 0; nt < 4; nt++) {
                acc_o[nt][0] *= s1; acc_o[nt][1] *= s1;
                acc_o[nt][2] *= s2; acc_o[nt][3] *= s2;
            }
        }
        const unsigned* Pu = (const unsigned*)Ss;
        #pragma unroll
        for (int kb = 0; kb < 64; kb += 8) {
            unsigned af[4], bf[4][2];
            int mr = wm * 16 + (lane >> 2);
            int kk = kb + (lane & 3);
            af[0] = Pu[mr * QPAD + kk];
            af[1] = Pu[(mr + 8) * QPAD + kk];
            af[2] = Pu[mr * QPAD + kk + 4];
            af[3] = Pu[(mr + 8) * QPAD + kk + 4];
            #pragma unroll
            for (int nt = 0; nt < 4; nt++) {
                int n = wn * 32 + nt * 8 + (lane >> 2);
                bf[nt][0] = Vs[(kb + (lane & 3)) * VPAD + n];
                bf[nt][1] = Vs[(kb + (lane & 3) + 4) * VPAD + n];
            }
            #pragma unroll
            for (int nt = 0; nt < 4; nt++)
                mma_tf32(acc_o[nt], af, bf[nt]);
        }
        __syncthreads();
    }

    {
        int r1 = wm * 16 + (lane >> 2);
        float inv1 = 1.0f / l_sm[r1], inv2 = 1.0f / l_sm[r1 + 8];
        #pragma unroll
        for (int nt = 0; nt < 4; nt++) {
            int c = wn * 32 + nt * 8 + 2 * (lane & 3);
            float* o1 = out + (size_t)(b * Tv + q0 + r1) * Dv + h * HDv + c;
            float* o2 = out + (size_t)(b * Tv + q0 + r1 + 8) * Dv + h * HDv + c;
            o1[0] = acc_o[nt][0] * inv1; o1[1] = acc_o[nt][1] * inv1;
            o2[0] = acc_o[nt][2] * inv2; o2[1] = acc_o[nt][3] * inv2;
        }
    }
}

// ---------------- driver ----------------
extern "C" void kernel_launch(void* const* d_in, const int* in_sizes, int n_in,
                              void* d_out, int out_size) {
    const int*   ids   = (const int*)  d_in[0];
    const float* te    = (const float*)d_in[1];
    const float* pe    = (const float*)d_in[2];
    const float* ln1_s = (const float*)d_in[3];
    const float* ln1_b = (const float*)d_in[4];
    const float* qkv_w = (const float*)d_in[5];
    const float* qkv_b = (const float*)d_in[6];
    const float* out_w = (const float*)d_in[7];
    const float* out_b = (const float*)d_in[8];
    const float* ln2_s = (const float*)d_in[9];
    const float* ln2_b = (const float*)d_in[10];
    const float* up_w  = (const float*)d_in[11];
    const float* up_b  = (const float*)d_in[12];
    const float* dn_w  = (const float*)d_in[13];
    const float* dn_b  = (const float*)d_in[14];
    const float* lnf_s = (const float*)d_in[15];
    const float* lnf_b = (const float*)d_in[16];
    float* logits = (float*)d_out;

    float *x, *lnb, *qkv, *att, *ff;
    cudaGetSymbolAddress((void**)&x,   g_x);
    cudaGetSymbolAddress((void**)&lnb, g_ln);
    cudaGetSymbolAddress((void**)&qkv, g_qkv);
    cudaGetSymbolAddress((void**)&att, g_att);
    cudaGetSymbolAddress((void**)&ff,  g_ff);

    cudaFuncSetAttribute(attn_flash_k,
                         cudaFuncAttributeMaxDynamicSharedMemorySize, ATTN_SMEM);

    embed_k<<<(Mv * Dv + 255) / 256, 256>>>(ids, te, pe, x);

    for (int i = 0; i < Lv; i++) {
        ln_k<<<Mv, 256>>>(x, ln1_s + (size_t)i * Dv, ln1_b + (size_t)i * Dv, lnb);
        gemm_tc<false, 0, false><<<dim3(QKVN / 128, Mv / 128), 256>>>(
            lnb, qkv_w + (size_t)i * Dv * QKVN, qkv_b + (size_t)i * QKVN,
            nullptr, qkv, Mv, QKVN, Dv);
        attn_flash_k<<<dim3(Tv / 64, Hv, Bv), 256, ATTN_SMEM>>>(qkv, att);
        gemm_tc<false, 0, true><<<dim3(Dv / 128, Mv / 128), 256>>>(
            att, out_w + (size_t)i * Dv * Dv, out_b + (size_t)i * Dv,
            x, x, Mv, Dv, Dv);
        ln_k<<<Mv, 256>>>(x, ln2_s + (size_t)i * Dv, ln2_b + (size_t)i * Dv, lnb);
        gemm_tc<false, 1, false><<<dim3(DFv / 128, Mv / 128), 256>>>(
            lnb, up_w + (size_t)i * Dv * DFv, up_b + (size_t)i * DFv,
            nullptr, ff, Mv, DFv, Dv);
        gemm_tc<false, 0, true><<<dim3(Dv / 128, Mv / 128), 256>>>(
            ff, dn_w + (size_t)i * DFv * Dv, dn_b + (size_t)i * Dv,
            x, x, Mv, Dv, DFv);
    }

    ln_k<<<Mv, 256>>>(x, lnf_s, lnf_b, lnb);
    gemm_tc<true, 0, false><<<dim3(Vv / 128, Mv / 128), 256>>>(
        lnb, te, nullptr, nullptr, logits, Mv, Vv, Dv);
}